// round 1
// baseline (speedup 1.0000x reference)
#include <cuda_runtime.h>
#include <math.h>
#include <stdint.h>

#define R        2048
#define KCLS     20
#define NSC      21          // K+1 score columns
#define IMGW     1333.0f
#define IMGH     800.0f
#define SCORE_TH 0.5f
#define NMS_TH   0.5f
#define TOPK     100
#define NEG_INF  __int_as_float(0xFF800000)

// masked score matrix [KCLS][R], class-major (matches scores_fg.T.reshape(-1))
__device__ float g_masked[KCLS * R];

// monotone map float -> uint (order-preserving, handles -inf)
__device__ __forceinline__ unsigned int fkey(float f) {
    unsigned int u = __float_as_uint(f);
    return (u & 0x80000000u) ? ~u : (u | 0x80000000u);
}
__device__ __forceinline__ float fkey_inv(unsigned int k) {
    unsigned int bits = (k & 0x80000000u) ? (k ^ 0x80000000u) : ~k;
    return __uint_as_float(bits);
}

// ---------------------------------------------------------------------------
// Kernel 1: per-class sort + greedy NMS.  grid = KCLS blocks, 1024 threads.
// ---------------------------------------------------------------------------
// dynamic smem layout:
//   skey   : 2048 * u64   (16384 B)
//   sx1..sy2 sorted clipped boxes (SoA) : 4 * 2048 * f32 (32768 B)
//   valpre : 2048 B   (validity by original index)
//   sval   : 2048 B   (validity in sorted order)
//   kx1,ky1,kx2,ky2,karea : 5 * 2048 * f32 (40960 B)  (kept list)
#define SMEM1_BYTES (16384 + 32768 + 4096 + 40960)

__global__ void __launch_bounds__(1024, 1)
nms_per_class_kernel(const float* __restrict__ boxes,
                     const float* __restrict__ scores)
{
    extern __shared__ unsigned char smem[];
    unsigned long long* skey = (unsigned long long*)smem;
    float* sx1 = (float*)(smem + 16384);
    float* sy1 = sx1 + R;
    float* sx2 = sy1 + R;
    float* sy2 = sx2 + R;
    unsigned char* valpre = (unsigned char*)(sy2 + R);
    unsigned char* sval   = valpre + R;
    float* kx1 = (float*)(sval + R);
    float* ky1 = kx1 + R;
    float* kx2 = ky1 + R;
    float* ky2 = kx2 + R;
    float* karea = ky2 + R;

    const int c = blockIdx.x;
    const int t = threadIdx.x;

    // ---- phase 1: keys, validity, init masked output ----
    for (int r = t; r < R; r += 1024) {
        bool fin = true;
        #pragma unroll
        for (int q = 0; q < 4; q++) fin &= isfinite(boxes[r * 4 + q]);
        for (int q = 0; q < NSC; q++) fin &= isfinite(scores[r * NSC + q]);
        float s = scores[r * NSC + c];
        valpre[r] = (fin && (s > SCORE_TH)) ? 1 : 0;
        skey[r] = ((unsigned long long)fkey(s) << 32) |
                  (unsigned long long)(0xFFFFFFFFu - (unsigned)r);
        g_masked[c * R + r] = NEG_INF;
    }
    __syncthreads();

    // ---- phase 2: bitonic sort, descending by composite key ----
    for (unsigned int kk = 2; kk <= (unsigned)R; kk <<= 1) {
        for (unsigned int j = kk >> 1; j > 0; j >>= 1) {
            #pragma unroll
            for (int e = 0; e < 2; e++) {
                unsigned int i = (unsigned)t + (unsigned)e * 1024u;
                unsigned int ixj = i ^ j;
                if (ixj > i) {
                    unsigned long long a = skey[i], b = skey[ixj];
                    bool descBlock = ((i & kk) == 0);
                    bool doSwap = descBlock ? (a < b) : (a > b);
                    if (doSwap) { skey[i] = b; skey[ixj] = a; }
                }
            }
            __syncthreads();
        }
    }

    // ---- phase 3: gather clipped boxes + validity into sorted order ----
    for (int i = t; i < R; i += 1024) {
        unsigned int rr = 0xFFFFFFFFu - (unsigned int)(skey[i] & 0xFFFFFFFFull);
        float x1 = fminf(fmaxf(boxes[rr * 4 + 0], 0.0f), IMGW);
        float y1 = fminf(fmaxf(boxes[rr * 4 + 1], 0.0f), IMGH);
        float x2 = fminf(fmaxf(boxes[rr * 4 + 2], 0.0f), IMGW);
        float y2 = fminf(fmaxf(boxes[rr * 4 + 3], 0.0f), IMGH);
        sx1[i] = x1; sy1[i] = y1; sx2[i] = x2; sy2[i] = y2;
        sval[i] = valpre[rr];
    }
    __syncthreads();

    // ---- phase 4: greedy NMS scan (warp 0) ----
    if (t < 32) {
        const int lane = t;
        int nk = 0;
        for (int i = 0; i < R; i++) {
            if (!sval[i]) continue;
            float x1 = sx1[i], y1 = sy1[i], x2 = sx2[i], y2 = sy2[i];
            float ai = (x2 - x1) * (y2 - y1);
            bool loc = false;
            for (int m = lane; m < nk; m += 32) {
                float xx1 = fmaxf(x1, kx1[m]);
                float yy1 = fmaxf(y1, ky1[m]);
                float xx2 = fminf(x2, kx2[m]);
                float yy2 = fminf(y2, ky2[m]);
                float w = fmaxf(xx2 - xx1, 0.0f);
                float h = fmaxf(yy2 - yy1, 0.0f);
                float inter = w * h;
                float uni = ai + karea[m] - inter;
                float iou = inter / fmaxf(uni, 1e-9f);
                loc |= (iou > NMS_TH);
            }
            bool sup = __any_sync(0xFFFFFFFFu, loc);
            if (!sup) {
                if (lane == 0) {
                    kx1[nk] = x1; ky1[nk] = y1; kx2[nk] = x2; ky2[nk] = y2;
                    karea[nk] = ai;
                    unsigned long long key = skey[i];
                    unsigned int rr = 0xFFFFFFFFu - (unsigned int)(key & 0xFFFFFFFFull);
                    g_masked[c * R + rr] = fkey_inv((unsigned int)(key >> 32));
                }
                nk++;
                __syncwarp(0xFFFFFFFFu);
            }
        }
    }
}

// ---------------------------------------------------------------------------
// Kernel 2: exact global top-100 over g_masked[K*R], lax.top_k semantics.
// grid = 1 block, 1024 threads.  Stripe of 40 per thread.
// ---------------------------------------------------------------------------
#define NTOT   (KCLS * R)      // 40960
#define STRIPE 40
#define SMEM2_BYTES (NTOT * 4 + 32 * 8 + 8)

__global__ void __launch_bounds__(1024, 1)
topk_kernel(const float* __restrict__ boxes, float* __restrict__ out)
{
    extern __shared__ unsigned char smem[];
    float* sdata = (float*)smem;                         // 40960 floats
    unsigned long long* swarp = (unsigned long long*)(smem + NTOT * 4);  // 32
    unsigned long long* swin  = swarp + 32;

    const int t = threadIdx.x;
    const int lane = t & 31;
    const int wid = t >> 5;

    for (int i = t; i < NTOT; i += 1024) sdata[i] = g_masked[i];
    __syncthreads();

    const int base = t * STRIPE;
    unsigned long long best = 0ull;
    #pragma unroll
    for (int m = 0; m < STRIPE; m++) {
        int flat = base + m;
        unsigned long long k = ((unsigned long long)fkey(sdata[flat]) << 32) |
                               (unsigned long long)(0xFFFFFFFFu - (unsigned)flat);
        best = (k > best) ? k : best;
    }

    for (int it = 0; it < TOPK; it++) {
        unsigned long long k = best;
        #pragma unroll
        for (int off = 16; off > 0; off >>= 1) {
            unsigned long long o = __shfl_down_sync(0xFFFFFFFFu, k, off);
            k = (o > k) ? o : k;
        }
        if (lane == 0) swarp[wid] = k;
        __syncthreads();
        if (t < 32) {
            unsigned long long k2 = swarp[t];
            #pragma unroll
            for (int off = 16; off > 0; off >>= 1) {
                unsigned long long o = __shfl_down_sync(0xFFFFFFFFu, k2, off);
                k2 = (o > k2) ? o : k2;
            }
            if (t == 0) swin[0] = k2;
        }
        __syncthreads();
        unsigned long long wk = swin[0];
        unsigned int flat = 0xFFFFFFFFu - (unsigned int)(wk & 0xFFFFFFFFull);

        if (t == 0) {
            float sc = fkey_inv((unsigned int)(wk >> 32));
            int cls = (int)(flat >> 11);      // R = 2048 = 2^11
            int rr  = (int)(flat & 2047u);
            out[it] = sc;
            out[TOPK + it * 4 + 0] = fminf(fmaxf(boxes[rr * 4 + 0], 0.0f), IMGW);
            out[TOPK + it * 4 + 1] = fminf(fmaxf(boxes[rr * 4 + 1], 0.0f), IMGH);
            out[TOPK + it * 4 + 2] = fminf(fmaxf(boxes[rr * 4 + 2], 0.0f), IMGW);
            out[TOPK + it * 4 + 3] = fminf(fmaxf(boxes[rr * 4 + 3], 0.0f), IMGH);
            out[TOPK + TOPK * 4 + it]        = (float)cls;
            out[TOPK + TOPK * 4 + TOPK + it] = (float)rr;
        }
        if ((int)flat >= base && (int)flat < base + STRIPE) {
            sdata[flat] = NEG_INF;
            best = 0ull;
            #pragma unroll
            for (int m = 0; m < STRIPE; m++) {
                int f2 = base + m;
                unsigned long long kk = ((unsigned long long)fkey(sdata[f2]) << 32) |
                                        (unsigned long long)(0xFFFFFFFFu - (unsigned)f2);
                best = (kk > best) ? kk : best;
            }
        }
        // swin/swarp reuse is safe: every thread reads swin before the next
        // iteration's first __syncthreads, and writes happen after it.
    }
}

extern "C" void kernel_launch(void* const* d_in, const int* in_sizes, int n_in,
                              void* d_out, int out_size)
{
    const float* boxes  = (const float*)d_in[0];   // [2048,4]
    const float* scores = (const float*)d_in[1];   // [2048,21]
    float* out = (float*)d_out;                    // 100 + 400 + 100 + 100 = 700

    cudaFuncSetAttribute(nms_per_class_kernel,
                         cudaFuncAttributeMaxDynamicSharedMemorySize, SMEM1_BYTES);
    cudaFuncSetAttribute(topk_kernel,
                         cudaFuncAttributeMaxDynamicSharedMemorySize, SMEM2_BYTES);

    nms_per_class_kernel<<<KCLS, 1024, SMEM1_BYTES>>>(boxes, scores);
    topk_kernel<<<1, 1024, SMEM2_BYTES>>>(boxes, out);
}

// round 3
// speedup vs baseline: 9.1968x; 9.1968x over previous
#include <cuda_runtime.h>
#include <math.h>
#include <stdint.h>

#define R        2048
#define WORDS    32          // R / 64
#define KCLS     20
#define NSC      21
#define IMGW     1333.0f
#define IMGH     800.0f
#define SCORE_TH 0.5f
#define NMS_TH   0.5f
#define TOPK     100
#define NEG_INF  __int_as_float(0xFF800000)

// ---------------- global scratch ----------------
__device__ float              g_masked[KCLS * R];        // class-major masked scores
__device__ unsigned long long g_skey  [KCLS * R];        // sorted composite keys (per-class r tiebreak)
__device__ float              g_sbox  [KCLS * 4 * R];    // sorted clipped boxes SoA
__device__ unsigned int       g_sval32[KCLS * 64];       // validity bits, sorted order
__device__ unsigned long long g_mask  [(size_t)KCLS * WORDS * R]; // [cls][word][row]
__device__ unsigned long long g_kept  [KCLS * R];        // kept keys (global-flat tiebreak), sorted
__device__ int                g_kcnt  [KCLS];

__device__ __forceinline__ unsigned int fkey(float f) {
    unsigned int u = __float_as_uint(f);
    return (u & 0x80000000u) ? ~u : (u | 0x80000000u);
}
__device__ __forceinline__ float fkey_inv(unsigned int k) {
    unsigned int bits = (k & 0x80000000u) ? (k ^ 0x80000000u) : ~k;
    return __uint_as_float(bits);
}

// ---------------------------------------------------------------------------
// Kernel 1: per-class bitonic sort; emit sorted keys/boxes/validity to global.
// grid = KCLS, block = 1024
// ---------------------------------------------------------------------------
__global__ void __launch_bounds__(1024, 1)
sort_kernel(const float* __restrict__ boxes, const float* __restrict__ scores)
{
    __shared__ unsigned long long skey[R];     // 16 KB
    __shared__ unsigned char     valpre[R];    // 2 KB

    const int c = blockIdx.x;
    const int t = threadIdx.x;

    for (int r = t; r < R; r += 1024) {
        bool fin = true;
        #pragma unroll
        for (int q = 0; q < 4; q++) fin &= isfinite(boxes[r * 4 + q]);
        for (int q = 0; q < NSC; q++) fin &= isfinite(scores[r * NSC + q]);
        float s = scores[r * NSC + c];
        valpre[r] = (fin && (s > SCORE_TH)) ? 1 : 0;
        skey[r] = ((unsigned long long)fkey(s) << 32) |
                  (unsigned long long)(0xFFFFFFFFu - (unsigned)r);
        g_masked[c * R + r] = NEG_INF;
    }
    __syncthreads();

    // bitonic sort, descending (equal scores -> smaller r first, matching
    // stable argsort(-scores))
    for (unsigned int kk = 2; kk <= (unsigned)R; kk <<= 1) {
        for (unsigned int j = kk >> 1; j > 0; j >>= 1) {
            #pragma unroll
            for (int e = 0; e < 2; e++) {
                unsigned int i = (unsigned)t + (unsigned)e * 1024u;
                unsigned int ixj = i ^ j;
                if (ixj > i) {
                    unsigned long long a = skey[i], b = skey[ixj];
                    bool descBlock = ((i & kk) == 0);
                    if (descBlock ? (a < b) : (a > b)) { skey[i] = b; skey[ixj] = a; }
                }
            }
            __syncthreads();
        }
    }

    // gather: sorted clipped boxes, validity ballots, keys -> global
    #pragma unroll
    for (int e = 0; e < 2; e++) {
        int i = t + e * 1024;
        unsigned long long key = skey[i];
        unsigned int rr = 0xFFFFFFFFu - (unsigned int)(key & 0xFFFFFFFFull);
        float x1 = fminf(fmaxf(boxes[rr * 4 + 0], 0.0f), IMGW);
        float y1 = fminf(fmaxf(boxes[rr * 4 + 1], 0.0f), IMGH);
        float x2 = fminf(fmaxf(boxes[rr * 4 + 2], 0.0f), IMGW);
        float y2 = fminf(fmaxf(boxes[rr * 4 + 3], 0.0f), IMGH);
        g_sbox[c * 4 * R + 0 * R + i] = x1;
        g_sbox[c * 4 * R + 1 * R + i] = y1;
        g_sbox[c * 4 * R + 2 * R + i] = x2;
        g_sbox[c * 4 * R + 3 * R + i] = y2;
        g_skey[c * R + i] = key;
        bool v = valpre[rr] != 0;
        unsigned int ball = __ballot_sync(0xFFFFFFFFu, v);
        if ((t & 31) == 0) g_sval32[c * 64 + (i >> 5)] = ball;
    }
}

// ---------------------------------------------------------------------------
// Kernel 2: IoU suppression bitmask.  grid = (R/32, KCLS), block = 1024.
// warp w = 64-column word, lane = row within 32-row chunk.
// mask[cls][w][row] bit k  <=>  IoU(row, w*64+k) > 0.5
// ---------------------------------------------------------------------------
__global__ void __launch_bounds__(1024, 1)
iou_mask_kernel()
{
    __shared__ float sb[4 * R];   // 32 KB sorted boxes SoA
    const int cls = blockIdx.y;
    const int rb  = blockIdx.x * 32;

    for (int i = threadIdx.x; i < 4 * R; i += 1024)
        sb[i] = g_sbox[cls * 4 * R + i];
    __syncthreads();

    const float* sx1 = sb;
    const float* sy1 = sb + R;
    const float* sx2 = sb + 2 * R;
    const float* sy2 = sb + 3 * R;

    const int w    = threadIdx.x >> 5;
    const int lane = threadIdx.x & 31;
    const int j    = rb + lane;

    unsigned long long bits = 0ull;
    // only columns c > row j can matter; skip words entirely at/below row chunk
    if ((w << 6) + 63 > rb) {
        float x1 = sx1[j], y1 = sy1[j], x2 = sx2[j], y2 = sy2[j];
        float aj = (x2 - x1) * (y2 - y1);
        #pragma unroll 8
        for (int k = 0; k < 64; k++) {
            int cix = (w << 6) + k;                 // broadcast reads
            float cx1 = sx1[cix], cy1 = sy1[cix], cx2 = sx2[cix], cy2 = sy2[cix];
            float xx1 = fmaxf(x1, cx1);
            float yy1 = fmaxf(y1, cy1);
            float xx2 = fminf(x2, cx2);
            float yy2 = fminf(y2, cy2);
            float ww = fmaxf(xx2 - xx1, 0.0f);
            float hh = fmaxf(yy2 - yy1, 0.0f);
            float inter = ww * hh;
            float ac = (cx2 - cx1) * (cy2 - cy1);
            float uni = aj + ac - inter;
            float iou = inter / fmaxf(uni, 1e-9f);
            bits |= ((unsigned long long)(iou > NMS_TH)) << k;
        }
    }
    g_mask[((size_t)cls * WORDS + w) * R + j] = bits;
}

// ---------------------------------------------------------------------------
// Kernel 3: serial greedy reduce over the bitmask.  grid = KCLS, block = 32.
// lane l owns suppressed word l (u64) + validity word l.
// Kept keys re-packed with GLOBAL flat-index tiebreak (c*R + r) so the merge
// reproduces lax.top_k tie semantics exactly.
// ---------------------------------------------------------------------------
__global__ void __launch_bounds__(32, 1)
nms_reduce_kernel()
{
    __shared__ unsigned long long skeys[R];    // 16 KB
    const int c = blockIdx.x;
    const int lane = threadIdx.x;

    for (int i = lane; i < R; i += 32) skeys[i] = g_skey[c * R + i];
    unsigned long long valid =
        ((unsigned long long)g_sval32[c * 64 + 2 * lane + 1] << 32) |
        (unsigned long long)g_sval32[c * 64 + 2 * lane];
    __syncwarp();

    unsigned long long supp = 0ull;
    int cnt = 0;

    for (int w = 0; w < WORDS; w++) {
        unsigned long long done = 0ull;
        while (true) {
            unsigned long long cand =
                __shfl_sync(0xFFFFFFFFu, valid & ~supp, w) & ~done;
            if (cand == 0ull) break;
            int b = __ffsll((unsigned long long)cand) - 1;
            int j = (w << 6) + b;
            // kept: OR its suppression row (one word per lane)
            supp |= g_mask[((size_t)c * WORDS + lane) * R + j];
            done |= (b == 63) ? ~0ull : ((1ull << (b + 1)) - 1ull);
            if (lane == 0) {
                unsigned long long key = skeys[j];
                unsigned int rr = 0xFFFFFFFFu - (unsigned int)(key & 0xFFFFFFFFull);
                unsigned int flat = (unsigned)c * R + rr;   // global flat index
                g_kept[c * R + cnt] =
                    (key & 0xFFFFFFFF00000000ull) |
                    (unsigned long long)(0xFFFFFFFFu - flat);
                g_masked[flat] = fkey_inv((unsigned int)(key >> 32));
            }
            cnt++;
        }
    }
    if (lane == 0) g_kcnt[c] = cnt;
}

// ---------------------------------------------------------------------------
// Kernel 4: 20-way merge of sorted kept lists -> exact top-100 + outputs.
// grid = 1, block = 128.
// ---------------------------------------------------------------------------
__global__ void __launch_bounds__(128, 1)
merge_topk_kernel(const float* __restrict__ boxes, float* __restrict__ out)
{
    __shared__ unsigned long long sheads[KCLS * TOPK];   // 16 KB
    __shared__ unsigned long long outk[TOPK];
    __shared__ int scnt[KCLS];

    const int t = threadIdx.x;
    if (t < KCLS) scnt[t] = g_kcnt[t];
    __syncthreads();

    for (int i = t; i < KCLS * TOPK; i += 128) {
        int c = i / TOPK, p = i % TOPK;
        int n = scnt[c]; if (n > TOPK) n = TOPK;
        sheads[i] = (p < n) ? g_kept[c * R + p] : 0ull;
    }
    __syncthreads();

    if (t < 32) {
        const int lane = t;
        unsigned long long mykey = 0ull;
        int ptr = 0, cap = 0;
        if (lane < KCLS) {
            cap = scnt[lane] < TOPK ? scnt[lane] : TOPK;
            mykey = (cap > 0) ? sheads[lane * TOPK] : 0ull;
        }
        int filled = 0;
        for (int it = 0; it < TOPK; it++) {
            unsigned long long m = mykey;
            #pragma unroll
            for (int off = 16; off > 0; off >>= 1) {
                unsigned long long o = __shfl_xor_sync(0xFFFFFFFFu, m, off);
                m = (o > m) ? o : m;
            }
            if (m == 0ull) break;                 // all lists exhausted
            if (mykey == m) {                      // unique winner (flat unique)
                ptr++;
                mykey = (ptr < cap) ? sheads[lane * TOPK + ptr] : 0ull;
            }
            if (lane == 0) outk[it] = m;
            filled = it + 1;
        }
        // degenerate fallback: fewer than TOPK kept -> -inf entries, lowest flat first
        if (lane == 0 && filled < TOPK) {
            int flat = 0;
            for (int it = filled; it < TOPK; it++) {
                while (flat < KCLS * R && g_masked[flat] != NEG_INF) flat++;
                outk[it] = ((unsigned long long)fkey(NEG_INF) << 32) |
                           (unsigned long long)(0xFFFFFFFFu - (unsigned)flat);
                flat++;
            }
        }
    }
    __syncthreads();

    if (t < TOPK) {
        unsigned long long key = outk[t];
        unsigned int flat = 0xFFFFFFFFu - (unsigned int)(key & 0xFFFFFFFFull);
        float sc = fkey_inv((unsigned int)(key >> 32));
        int cls = (int)(flat >> 11);      // R = 2048 = 2^11
        int rr  = (int)(flat & 2047u);
        out[t] = sc;
        out[TOPK + t * 4 + 0] = fminf(fmaxf(boxes[rr * 4 + 0], 0.0f), IMGW);
        out[TOPK + t * 4 + 1] = fminf(fmaxf(boxes[rr * 4 + 1], 0.0f), IMGH);
        out[TOPK + t * 4 + 2] = fminf(fmaxf(boxes[rr * 4 + 2], 0.0f), IMGW);
        out[TOPK + t * 4 + 3] = fminf(fmaxf(boxes[rr * 4 + 3], 0.0f), IMGH);
        out[TOPK + TOPK * 4 + t]        = (float)cls;
        out[TOPK + TOPK * 4 + TOPK + t] = (float)rr;
    }
}

extern "C" void kernel_launch(void* const* d_in, const int* in_sizes, int n_in,
                              void* d_out, int out_size)
{
    const float* boxes  = (const float*)d_in[0];   // [2048,4]
    const float* scores = (const float*)d_in[1];   // [2048,21]
    float* out = (float*)d_out;

    sort_kernel<<<KCLS, 1024>>>(boxes, scores);
    iou_mask_kernel<<<dim3(R / 32, KCLS), 1024>>>();
    nms_reduce_kernel<<<KCLS, 32>>>();
    merge_topk_kernel<<<1, 128>>>(boxes, out);
}